// round 1
// baseline (speedup 1.0000x reference)
#include <cuda_runtime.h>
#include <cuda_bf16.h>

#define N_NODES   10000
#define N_EDGES   640000
#define F_IN      128
#define H1        64
#define H2        32
#define N_CLASSES 16

// ---------------- scratch (device globals; no allocation allowed) ----------
__device__ float g_h1  [N_NODES * H1];   // x @ W1
__device__ float g_agg1[N_NODES * H1];   // neighbor agg (then relu'd h, in place)
__device__ float g_h2  [N_NODES * H2];   // h @ W2
__device__ float g_agg2[N_NODES * H2];   // neighbor agg layer 2
__device__ float g_deg [N_NODES];
__device__ float g_dinv[N_NODES];
__device__ float g_colsum[H2];

// vectorized L2 reduction (no return), sm_90+
__device__ __forceinline__ void red_add_v4(float4* addr, float4 v) {
    asm volatile("red.global.add.v4.f32 [%0], {%1,%2,%3,%4};"
                 :: "l"(addr), "f"(v.x), "f"(v.y), "f"(v.z), "f"(v.w)
                 : "memory");
}

// ---------------- kernels ---------------------------------------------------

// zero all accumulators (graph replays reuse buffers, must re-zero every launch)
__global__ void zero_kernel() {
    int t = blockIdx.x * blockDim.x + threadIdx.x;
    if (t < N_NODES * H1) g_agg1[t] = 0.0f;
    if (t < N_NODES * H2) g_agg2[t] = 0.0f;
    if (t < N_NODES)      g_deg[t]  = 0.0f;
    if (t < H2)           g_colsum[t] = 0.0f;
}

__global__ void deg_kernel(const int* __restrict__ ei) {
    int e = blockIdx.x * blockDim.x + threadIdx.x;
    if (e >= N_EDGES) return;
    int dst = ei[N_EDGES + e];
    atomicAdd(&g_deg[dst], 1.0f);
}

__global__ void dinv_kernel() {
    int n = blockIdx.x * blockDim.x + threadIdx.x;
    if (n >= N_NODES) return;
    g_dinv[n] = rsqrtf(g_deg[n] + 1.0f);
}

// h1 = x @ W1 : [10000,128] @ [128,64]. 4 threads per node, 16 outputs each.
__global__ void gemm1_kernel(const float* __restrict__ x,
                             const float* __restrict__ W1) {
    __shared__ float Ws[F_IN * H1];  // 32 KB
    for (int i = threadIdx.x; i < F_IN * H1; i += blockDim.x) Ws[i] = W1[i];
    __syncthreads();

    int gt   = blockIdx.x * blockDim.x + threadIdx.x;
    int node = gt >> 2;
    int q    = gt & 3;                 // output slice [q*16, q*16+16)
    if (node >= N_NODES) return;

    float acc[16];
#pragma unroll
    for (int j = 0; j < 16; j++) acc[j] = 0.0f;

    const float* xr = x + node * F_IN;
#pragma unroll 4
    for (int k = 0; k < F_IN; k++) {
        float xv = __ldg(xr + k);
        const float4* wrow = (const float4*)(Ws + k * H1 + q * 16);
#pragma unroll
        for (int j = 0; j < 4; j++) {
            float4 w = wrow[j];
            acc[4*j+0] += xv * w.x;
            acc[4*j+1] += xv * w.y;
            acc[4*j+2] += xv * w.z;
            acc[4*j+3] += xv * w.w;
        }
    }
    float4* o = (float4*)(g_h1 + node * H1 + q * 16);
#pragma unroll
    for (int j = 0; j < 4; j++)
        o[j] = make_float4(acc[4*j], acc[4*j+1], acc[4*j+2], acc[4*j+3]);
}

// edge aggregation layer 1: 16 threads per edge, float4 each (64 feats)
__global__ void agg1_kernel(const int* __restrict__ ei) {
    long long t = (long long)blockIdx.x * blockDim.x + threadIdx.x;
    int e = (int)(t >> 4);
    int q = (int)(t & 15);
    if (e >= N_EDGES) return;
    int src = ei[e];
    int dst = ei[N_EDGES + e];
    float c = g_dinv[src] * g_dinv[dst];
    float4 v = ((const float4*)g_h1)[src * 16 + q];
    v.x *= c; v.y *= c; v.z *= c; v.w *= c;
    red_add_v4(&((float4*)g_agg1)[dst * 16 + q], v);
}

// agg1 += self-loop + bias, relu  (in place -> becomes layer-1 activations)
__global__ void post1_kernel(const float* __restrict__ b1) {
    int t = blockIdx.x * blockDim.x + threadIdx.x;
    if (t >= N_NODES * H1) return;
    int n = t >> 6;
    int f = t & 63;
    float d = g_dinv[n];
    float v = g_agg1[t] + g_h1[t] * (d * d) + b1[f];
    g_agg1[t] = fmaxf(v, 0.0f);
}

// h2 = h @ W2 : [10000,64] @ [64,32]. 4 threads per node, 8 outputs each.
__global__ void gemm2_kernel(const float* __restrict__ W2) {
    __shared__ float Ws[H1 * H2];  // 8 KB
    for (int i = threadIdx.x; i < H1 * H2; i += blockDim.x) Ws[i] = W2[i];
    __syncthreads();

    int gt   = blockIdx.x * blockDim.x + threadIdx.x;
    int node = gt >> 2;
    int q    = gt & 3;               // output slice [q*8, q*8+8)
    if (node >= N_NODES) return;

    float acc[8];
#pragma unroll
    for (int j = 0; j < 8; j++) acc[j] = 0.0f;

    const float* hr = g_agg1 + node * H1;
#pragma unroll 4
    for (int k = 0; k < H1; k++) {
        float xv = hr[k];
        const float4* wrow = (const float4*)(Ws + k * H2 + q * 8);
#pragma unroll
        for (int j = 0; j < 2; j++) {
            float4 w = wrow[j];
            acc[4*j+0] += xv * w.x;
            acc[4*j+1] += xv * w.y;
            acc[4*j+2] += xv * w.z;
            acc[4*j+3] += xv * w.w;
        }
    }
    float4* o = (float4*)(g_h2 + node * H2 + q * 8);
    o[0] = make_float4(acc[0], acc[1], acc[2], acc[3]);
    o[1] = make_float4(acc[4], acc[5], acc[6], acc[7]);
}

// edge aggregation layer 2: 8 threads per edge, float4 each (32 feats)
__global__ void agg2_kernel(const int* __restrict__ ei) {
    long long t = (long long)blockIdx.x * blockDim.x + threadIdx.x;
    int e = (int)(t >> 3);
    int q = (int)(t & 7);
    if (e >= N_EDGES) return;
    int src = ei[e];
    int dst = ei[N_EDGES + e];
    float c = g_dinv[src] * g_dinv[dst];
    float4 v = ((const float4*)g_h2)[src * 8 + q];
    v.x *= c; v.y *= c; v.z *= c; v.w *= c;
    red_add_v4(&((float4*)g_agg2)[dst * 8 + q], v);
}

// layer-2 epilogue: bias + self-loop + relu, then column sums into g_colsum
__global__ void post2_kernel(const float* __restrict__ b2) {
    __shared__ float s[256];
    int t = blockIdx.x * blockDim.x + threadIdx.x;  // over N_NODES*H2 = 320000
    int n = t >> 5;
    int f = t & 31;
    float v = 0.0f;
    if (t < N_NODES * H2) {
        float d = g_dinv[n];
        v = fmaxf(g_agg2[t] + g_h2[t] * (d * d) + b2[f], 0.0f);
    }
    s[threadIdx.x] = v;
    __syncthreads();
    // reduce over the 8 nodes in this block (stride multiples of 32 keep f fixed)
#pragma unroll
    for (int st = 128; st >= 32; st >>= 1) {
        if (threadIdx.x < st) s[threadIdx.x] += s[threadIdx.x + st];
        __syncthreads();
    }
    if (threadIdx.x < 32) atomicAdd(&g_colsum[threadIdx.x], s[threadIdx.x]);
}

// out = (colsum / N) @ Wfc + bfc
__global__ void final_kernel(const float* __restrict__ Wfc,
                             const float* __restrict__ bfc,
                             float* __restrict__ out) {
    int c = threadIdx.x;
    if (c >= N_CLASSES) return;
    float acc = bfc[c];
    const float inv_n = 1.0f / (float)N_NODES;
#pragma unroll
    for (int f = 0; f < H2; f++)
        acc += (g_colsum[f] * inv_n) * Wfc[f * N_CLASSES + c];
    out[c] = acc;
}

// ---------------- launch ----------------------------------------------------
extern "C" void kernel_launch(void* const* d_in, const int* in_sizes, int n_in,
                              void* d_out, int out_size) {
    const float* x   = (const float*)d_in[0];
    const float* W1  = (const float*)d_in[1];
    const float* b1  = (const float*)d_in[2];
    const float* W2  = (const float*)d_in[3];
    const float* b2  = (const float*)d_in[4];
    const float* Wfc = (const float*)d_in[5];
    const float* bfc = (const float*)d_in[6];
    const int*   ei  = (const int*)  d_in[7];
    float* out = (float*)d_out;

    const int B = 256;

    zero_kernel<<<(N_NODES * H1 + B - 1) / B, B>>>();
    deg_kernel<<<(N_EDGES + B - 1) / B, B>>>(ei);
    dinv_kernel<<<(N_NODES + B - 1) / B, B>>>();

    gemm1_kernel<<<(N_NODES * 4 + B - 1) / B, B>>>(x, W1);

    {
        long long total = (long long)N_EDGES * 16;
        agg1_kernel<<<(unsigned)((total + B - 1) / B), B>>>(ei);
    }
    post1_kernel<<<(N_NODES * H1 + B - 1) / B, B>>>(b1);

    gemm2_kernel<<<(N_NODES * 4 + B - 1) / B, B>>>(W2);

    {
        long long total = (long long)N_EDGES * 8;
        agg2_kernel<<<(unsigned)((total + B - 1) / B), B>>>(ei);
    }
    post2_kernel<<<(N_NODES * H2 + B - 1) / B, B>>>(b2);

    final_kernel<<<1, 32>>>(Wfc, bfc, out);
}

// round 2
// speedup vs baseline: 1.3916x; 1.3916x over previous
#include <cuda_runtime.h>
#include <cuda_bf16.h>

#define N_NODES   10000
#define N_EDGES   640000
#define F_IN      128
#define H1        64
#define H2        32
#define N_CLASSES 16

// ---------------- scratch (device globals; no allocation allowed) ----------
__device__ float g_h1  [N_NODES * H1];   // x @ W1
__device__ float g_agg1[N_NODES * H1];   // neighbor agg (then relu'd h, in place)
__device__ float g_h2  [N_NODES * H2];   // h @ W2
__device__ float g_agg2[N_NODES * H2];   // neighbor agg layer 2
__device__ float g_deg [N_NODES];
__device__ float g_dinv[N_NODES];
__device__ float g_colsum[H2];

// vectorized L2 reduction (no return), sm_90+
__device__ __forceinline__ void red_add_v4(float4* addr, float4 v) {
    asm volatile("red.global.add.v4.f32 [%0], {%1,%2,%3,%4};"
                 :: "l"(addr), "f"(v.x), "f"(v.y), "f"(v.z), "f"(v.w)
                 : "memory");
}

// ---------------- kernels ---------------------------------------------------

__global__ void zero_kernel() {
    int t = blockIdx.x * blockDim.x + threadIdx.x;
    if (t < N_NODES * H1) g_agg1[t] = 0.0f;
    if (t < N_NODES * H2) g_agg2[t] = 0.0f;
    if (t < N_NODES)      g_deg[t]  = 0.0f;
    if (t < H2)           g_colsum[t] = 0.0f;
}

__global__ void deg_kernel(const int* __restrict__ ei) {
    int e = blockIdx.x * blockDim.x + threadIdx.x;
    if (e >= N_EDGES) return;
    atomicAdd(&g_deg[ei[N_EDGES + e]], 1.0f);
}

__global__ void dinv_kernel() {
    int n = blockIdx.x * blockDim.x + threadIdx.x;
    if (n >= N_NODES) return;
    g_dinv[n] = rsqrtf(g_deg[n] + 1.0f);
}

// ---------------------------------------------------------------------------
// gemm1: h1 = x @ W1  [10000,128]@[128,64]
// Block = 64 nodes x 32 outputs (blockIdx.y = output half), 256 threads.
// micro-tile: 2 nodes x 4 outs per thread. K tiled in 2 chunks of 64.
// Xs padded to 65 floats/row -> conflict-free scalar LDS.
__global__ __launch_bounds__(256) void gemm1_kernel(const float* __restrict__ x,
                                                    const float* __restrict__ W1) {
    __shared__ float Xs[64][65];   // [node_local][k_local]
    __shared__ float Ws[64][32];   // [k_local][out_local]

    const int tid  = threadIdx.x;
    const int tx   = tid & 7;      // 8 groups x 4 outputs = 32 outs
    const int ty   = tid >> 3;     // 32 groups x 2 nodes = 64 nodes
    const int node0 = blockIdx.x * 64;
    const int half  = blockIdx.y;  // 0 or 1 -> output cols [half*32, half*32+32)

    float acc[2][4];
#pragma unroll
    for (int i = 0; i < 2; i++)
#pragma unroll
        for (int j = 0; j < 4; j++) acc[i][j] = 0.0f;

    for (int kc = 0; kc < 2; kc++) {
        // load W chunk: rows [kc*64, kc*64+64), cols [half*32, +32) -> 2048 floats
        {
            int row = tid >> 3;          // 0..31
            int c4  = (tid & 7) * 4;     // 0..28
#pragma unroll
            for (int p = 0; p < 2; p++) {
                int r = row + p * 32;
                float4 w = *(const float4*)(W1 + (kc * 64 + r) * H1 + half * 32 + c4);
                *(float4*)(&Ws[r][c4]) = w;
            }
        }
        // load X chunk: 64 nodes x 64 k
        {
            int nl = tid >> 2;           // 0..63
            int k4 = (tid & 3) * 4;      // 0,4,8,12
            int node = node0 + nl;
#pragma unroll
            for (int p = 0; p < 4; p++) {
                int kk = k4 + p * 16;
                float4 v = make_float4(0.f, 0.f, 0.f, 0.f);
                if (node < N_NODES)
                    v = *(const float4*)(x + node * F_IN + kc * 64 + kk);
                Xs[nl][kk + 0] = v.x; Xs[nl][kk + 1] = v.y;
                Xs[nl][kk + 2] = v.z; Xs[nl][kk + 3] = v.w;
            }
        }
        __syncthreads();

#pragma unroll 8
        for (int k = 0; k < 64; k++) {
            float4 wv = *(const float4*)(&Ws[k][tx * 4]);
            float x0 = Xs[ty * 2 + 0][k];
            float x1 = Xs[ty * 2 + 1][k];
            acc[0][0] += x0 * wv.x; acc[0][1] += x0 * wv.y;
            acc[0][2] += x0 * wv.z; acc[0][3] += x0 * wv.w;
            acc[1][0] += x1 * wv.x; acc[1][1] += x1 * wv.y;
            acc[1][2] += x1 * wv.z; acc[1][3] += x1 * wv.w;
        }
        __syncthreads();
    }

#pragma unroll
    for (int i = 0; i < 2; i++) {
        int node = node0 + ty * 2 + i;
        if (node < N_NODES)
            *(float4*)(g_h1 + node * H1 + half * 32 + tx * 4) =
                make_float4(acc[i][0], acc[i][1], acc[i][2], acc[i][3]);
    }
}

// ---------------------------------------------------------------------------
// gemm2: h2 = h @ W2  [10000,64]@[64,32]  (h = g_agg1, relu'd layer-1 act)
// Block = 64 nodes x 32 outs, 256 threads, single K chunk (K=64).
__global__ __launch_bounds__(256) void gemm2_kernel(const float* __restrict__ W2) {
    __shared__ float Xs[64][65];
    __shared__ float Ws[64][32];

    const int tid = threadIdx.x;
    const int tx  = tid & 7;
    const int ty  = tid >> 3;
    const int node0 = blockIdx.x * 64;

    float acc[2][4];
#pragma unroll
    for (int i = 0; i < 2; i++)
#pragma unroll
        for (int j = 0; j < 4; j++) acc[i][j] = 0.0f;

    // load W2 full: 64x32 = 2048 floats
    {
        int row = tid >> 3;
        int c4  = (tid & 7) * 4;
#pragma unroll
        for (int p = 0; p < 2; p++) {
            int r = row + p * 32;
            *(float4*)(&Ws[r][c4]) = *(const float4*)(W2 + r * H2 + c4);
        }
    }
    // load X: 64 nodes x 64 feats from g_agg1
    {
        int nl = tid >> 2;
        int k4 = (tid & 3) * 4;
        int node = node0 + nl;
#pragma unroll
        for (int p = 0; p < 4; p++) {
            int kk = k4 + p * 16;
            float4 v = make_float4(0.f, 0.f, 0.f, 0.f);
            if (node < N_NODES)
                v = *(const float4*)(g_agg1 + node * H1 + kk);
            Xs[nl][kk + 0] = v.x; Xs[nl][kk + 1] = v.y;
            Xs[nl][kk + 2] = v.z; Xs[nl][kk + 3] = v.w;
        }
    }
    __syncthreads();

#pragma unroll 8
    for (int k = 0; k < 64; k++) {
        float4 wv = *(const float4*)(&Ws[k][tx * 4]);
        float x0 = Xs[ty * 2 + 0][k];
        float x1 = Xs[ty * 2 + 1][k];
        acc[0][0] += x0 * wv.x; acc[0][1] += x0 * wv.y;
        acc[0][2] += x0 * wv.z; acc[0][3] += x0 * wv.w;
        acc[1][0] += x1 * wv.x; acc[1][1] += x1 * wv.y;
        acc[1][2] += x1 * wv.z; acc[1][3] += x1 * wv.w;
    }

#pragma unroll
    for (int i = 0; i < 2; i++) {
        int node = node0 + ty * 2 + i;
        if (node < N_NODES)
            *(float4*)(g_h2 + node * H2 + tx * 4) =
                make_float4(acc[i][0], acc[i][1], acc[i][2], acc[i][3]);
    }
}

// ---------------------------------------------------------------------------
// edge aggregation layer 1: 16 threads per edge, float4 each (64 feats)
__global__ void agg1_kernel(const int* __restrict__ ei) {
    long long t = (long long)blockIdx.x * blockDim.x + threadIdx.x;
    int e = (int)(t >> 4);
    int q = (int)(t & 15);
    if (e >= N_EDGES) return;
    int src = ei[e];
    int dst = ei[N_EDGES + e];
    float c = g_dinv[src] * g_dinv[dst];
    float4 v = ((const float4*)g_h1)[src * 16 + q];
    v.x *= c; v.y *= c; v.z *= c; v.w *= c;
    red_add_v4(&((float4*)g_agg1)[dst * 16 + q], v);
}

// agg1 += self-loop + bias, relu  (in place -> layer-1 activations)
__global__ void post1_kernel(const float* __restrict__ b1) {
    int t = blockIdx.x * blockDim.x + threadIdx.x;
    if (t >= N_NODES * H1) return;
    int n = t >> 6;
    int f = t & 63;
    float d = g_dinv[n];
    float v = g_agg1[t] + g_h1[t] * (d * d) + b1[f];
    g_agg1[t] = fmaxf(v, 0.0f);
}

// edge aggregation layer 2: 8 threads per edge, float4 each (32 feats)
__global__ void agg2_kernel(const int* __restrict__ ei) {
    long long t = (long long)blockIdx.x * blockDim.x + threadIdx.x;
    int e = (int)(t >> 3);
    int q = (int)(t & 7);
    if (e >= N_EDGES) return;
    int src = ei[e];
    int dst = ei[N_EDGES + e];
    float c = g_dinv[src] * g_dinv[dst];
    float4 v = ((const float4*)g_h2)[src * 8 + q];
    v.x *= c; v.y *= c; v.z *= c; v.w *= c;
    red_add_v4(&((float4*)g_agg2)[dst * 8 + q], v);
}

// layer-2 epilogue: bias + self-loop + relu, then column sums into g_colsum
__global__ void post2_kernel(const float* __restrict__ b2) {
    __shared__ float s[256];
    int t = blockIdx.x * blockDim.x + threadIdx.x;
    int n = t >> 5;
    int f = t & 31;
    float v = 0.0f;
    if (t < N_NODES * H2) {
        float d = g_dinv[n];
        v = fmaxf(g_agg2[t] + g_h2[t] * (d * d) + b2[f], 0.0f);
    }
    s[threadIdx.x] = v;
    __syncthreads();
#pragma unroll
    for (int st = 128; st >= 32; st >>= 1) {
        if (threadIdx.x < st) s[threadIdx.x] += s[threadIdx.x + st];
        __syncthreads();
    }
    if (threadIdx.x < 32) atomicAdd(&g_colsum[threadIdx.x], s[threadIdx.x]);
}

// out = (colsum / N) @ Wfc + bfc
__global__ void final_kernel(const float* __restrict__ Wfc,
                             const float* __restrict__ bfc,
                             float* __restrict__ out) {
    int c = threadIdx.x;
    if (c >= N_CLASSES) return;
    float acc = bfc[c];
    const float inv_n = 1.0f / (float)N_NODES;
#pragma unroll
    for (int f = 0; f < H2; f++)
        acc += (g_colsum[f] * inv_n) * Wfc[f * N_CLASSES + c];
    out[c] = acc;
}

// ---------------- launch ----------------------------------------------------
extern "C" void kernel_launch(void* const* d_in, const int* in_sizes, int n_in,
                              void* d_out, int out_size) {
    const float* x   = (const float*)d_in[0];
    const float* W1  = (const float*)d_in[1];
    const float* b1  = (const float*)d_in[2];
    const float* W2  = (const float*)d_in[3];
    const float* b2  = (const float*)d_in[4];
    const float* Wfc = (const float*)d_in[5];
    const float* bfc = (const float*)d_in[6];
    const int*   ei  = (const int*)  d_in[7];
    float* out = (float*)d_out;

    const int B = 256;
    const int NODE_TILES = (N_NODES + 63) / 64;   // 157

    zero_kernel<<<(N_NODES * H1 + B - 1) / B, B>>>();
    deg_kernel<<<(N_EDGES + B - 1) / B, B>>>(ei);
    dinv_kernel<<<(N_NODES + B - 1) / B, B>>>();

    {
        dim3 grid(NODE_TILES, 2);  // 314 blocks: 64 nodes x 32-out half each
        gemm1_kernel<<<grid, 256>>>(x, W1);
    }

    {
        long long total = (long long)N_EDGES * 16;
        agg1_kernel<<<(unsigned)((total + B - 1) / B), B>>>(ei);
    }
    post1_kernel<<<(N_NODES * H1 + B - 1) / B, B>>>(b1);

    gemm2_kernel<<<NODE_TILES, 256>>>(W2);

    {
        long long total = (long long)N_EDGES * 8;
        agg2_kernel<<<(unsigned)((total + B - 1) / B), B>>>(ei);
    }
    post2_kernel<<<(N_NODES * H2 + B - 1) / B, B>>>(b2);

    final_kernel<<<1, 32>>>(Wfc, bfc, out);
}